// round 4
// baseline (speedup 1.0000x reference)
#include <cuda_runtime.h>
#include <cstdint>

// ---------------------------------------------------------------------------
// Shapes (fixed): T=16384, D=H=2880, E=8, C=2048, N1=5760. K=2880 both GEMMs.
// Strategy: pre-round all operands to tf32-exact fp32 once (RN), then run
// cvt-free mma.sync tf32 pipelines with 64x48 warp tiles and 4-stage cp.async.
// ---------------------------------------------------------------------------
#define KDIM 2880
#define BM 128
#define BN 192
#define NT 6               // n8-subtiles per warp -> warp tile 64 x 48
#define BK 32
#define NSTAGE 4
#define NKITER 90          // 2880/32
#define LDSF 36            // smem row pitch (floats); bank-conflict-free
#define A_FLOATS (BM * LDSF)
#define B_FLOATS (BN * LDSF)
#define STAGE_FLOATS (A_FLOATS + B_FLOATS)
#define SMEM_BYTES (NSTAGE * STAGE_FLOATS * 4)   // 184320

// Static scratch (tf32-rounded operands + activations)
__device__ float g_x[(size_t)16384 * 2880];
__device__ float g_w1[(size_t)8 * 5760 * 2880];
__device__ float g_w2[(size_t)8 * 2880 * 2880];
__device__ float g_act[(size_t)16384 * 2880];

__device__ __forceinline__ uint32_t s2u(const void* p) {
    uint32_t a;
    asm("{.reg .u64 t; cvta.to.shared.u64 t, %1; cvt.u32.u64 %0, t;}"
        : "=r"(a) : "l"(p));
    return a;
}
__device__ __forceinline__ float rtf32(float v) {
    uint32_t u;
    asm("cvt.rn.tf32.f32 %0, %1;" : "=r"(u) : "f"(v));
    return __uint_as_float(u);
}
__device__ __forceinline__ void cp16(uint32_t dst, const void* src) {
    asm volatile("cp.async.cg.shared.global [%0], [%1], 16;" ::"r"(dst),
                 "l"(src) : "memory");
}
__device__ __forceinline__ void mma_tf32(float* c, const uint32_t* a,
                                         const uint32_t* b) {
    asm volatile(
        "mma.sync.aligned.m16n8k8.row.col.f32.tf32.tf32.f32 "
        "{%0,%1,%2,%3}, {%4,%5,%6,%7}, {%8,%9}, {%0,%1,%2,%3};"
        : "+f"(c[0]), "+f"(c[1]), "+f"(c[2]), "+f"(c[3])
        : "r"(a[0]), "r"(a[1]), "r"(a[2]), "r"(a[3]), "r"(b[0]), "r"(b[1]));
}

// ---------------------------------------------------------------------------
// Pre-round: dst = round_to_tf32(src), float4 grid-stride
// ---------------------------------------------------------------------------
__global__ void round_tf32_kernel(const float4* __restrict__ src,
                                  float4* __restrict__ dst, size_t n4) {
    size_t i = (size_t)blockIdx.x * blockDim.x + threadIdx.x;
    size_t stride = (size_t)gridDim.x * blockDim.x;
    for (; i < n4; i += stride) {
        float4 v = src[i];
        v.x = rtf32(v.x); v.y = rtf32(v.y);
        v.z = rtf32(v.z); v.w = rtf32(v.w);
        dst[i] = v;
    }
}

// ---------------------------------------------------------------------------
// Grouped GEMM, CTA tile 128x192, 8 warps (2M x 4N), warp tile 64x48.
//   SWIGLU=true : h = g_x @ g_w1^T + b1, swiglu -> g_act (rounded to tf32)
//   SWIGLU=false: out = g_act @ g_w2^T + b2 -> d_out
// ---------------------------------------------------------------------------
template <bool SWIGLU>
__global__ __launch_bounds__(256, 1)
void moe_mma_kernel(const float* __restrict__ bias, float* __restrict__ Dout) {
    constexpr int ACH = 4;  // 128*8/256 cp.async chunks per thread (A)
    constexpr int BCH = 6;  // 192*8/256 (B)

    extern __shared__ float smem[];
    const uint32_t smem_u = s2u(smem);

    const int tid = threadIdx.x;
    const int lane = tid & 31;
    const int warp = tid >> 5;
    const int wm = warp & 1;   // 2 warps along M (64 rows)
    const int wn = warp >> 1;  // 4 warps along N (48 cols)

    const int bn = blockIdx.x, bm = blockIdx.y;
    const int e = bm >> 4;  // 16 m-tiles per expert
    const size_t row0 = (size_t)bm * BM;
    const int n0 = bn * BN;
    const int NBROWS = SWIGLU ? 5760 : 2880;

    const float* Abase = (SWIGLU ? g_x : g_act) + row0 * KDIM;
    const float* Bbase =
        (SWIGLU ? g_w1 : g_w2) + (size_t)e * NBROWS * KDIM + (size_t)n0 * KDIM;

    const float* gA[ACH];
    uint32_t sAo[ACH];
#pragma unroll
    for (int q = 0; q < ACH; q++) {
        int ch = tid + q * 256;
        int r = ch >> 3, c = ch & 7;
        gA[q] = Abase + (size_t)r * KDIM + c * 4;
        sAo[q] = (r * LDSF + c * 4) * 4;
    }
    const float* gB[BCH];
    uint32_t sBo[BCH];
#pragma unroll
    for (int q = 0; q < BCH; q++) {
        int ch = tid + q * 256;
        int r = ch >> 3, c = ch & 7;
        gB[q] = Bbase + (size_t)r * KDIM + c * 4;
        sBo[q] = (A_FLOATS + r * LDSF + c * 4) * 4;
    }

    // prologue: fill all stages
#pragma unroll
    for (int p = 0; p < NSTAGE; p++) {
        uint32_t sb = smem_u + p * STAGE_FLOATS * 4;
        int k0 = p * BK;
#pragma unroll
        for (int q = 0; q < ACH; q++) cp16(sb + sAo[q], gA[q] + k0);
#pragma unroll
        for (int q = 0; q < BCH; q++) cp16(sb + sBo[q], gB[q] + k0);
        asm volatile("cp.async.commit_group;" ::: "memory");
    }

    float acc[4][NT][4];
#pragma unroll
    for (int i = 0; i < 4; i++)
#pragma unroll
        for (int j = 0; j < NT; j++)
#pragma unroll
            for (int k = 0; k < 4; k++) acc[i][j][k] = 0.0f;

    const int arow = wm * 64 + (lane >> 2);
    const int kcol = lane & 3;
    const int brow = wn * 48 + (lane >> 2);

    int s = 0;
    for (int it = 0; it < NKITER; it++) {
        asm volatile("cp.async.wait_group %0;" ::"n"(NSTAGE - 1) : "memory");
        __syncthreads();
        const uint32_t* sA = (const uint32_t*)(smem + s * STAGE_FLOATS);
        const uint32_t* sB = sA + A_FLOATS;

#pragma unroll
        for (int kk8 = 0; kk8 < 4; kk8++) {
            const int kk = kk8 * 8;
            uint32_t af[4][4], bf[NT][2];
#pragma unroll
            for (int i = 0; i < 4; i++) {
                const uint32_t* ap = sA + (arow + i * 16) * LDSF + kk + kcol;
                af[i][0] = ap[0];
                af[i][1] = ap[8 * LDSF];
                af[i][2] = ap[4];
                af[i][3] = ap[8 * LDSF + 4];
            }
#pragma unroll
            for (int j = 0; j < NT; j++) {
                const uint32_t* bp = sB + (brow + j * 8) * LDSF + kk + kcol;
                bf[j][0] = bp[0];
                bf[j][1] = bp[4];
            }
#pragma unroll
            for (int i = 0; i < 4; i++)
#pragma unroll
                for (int j = 0; j < NT; j++) mma_tf32(acc[i][j], af[i], bf[j]);
        }
        __syncthreads();

        if (it + NSTAGE < NKITER) {
            uint32_t sb = smem_u + s * STAGE_FLOATS * 4;
            int k0 = (it + NSTAGE) * BK;
#pragma unroll
            for (int q = 0; q < ACH; q++) cp16(sb + sAo[q], gA[q] + k0);
#pragma unroll
            for (int q = 0; q < BCH; q++) cp16(sb + sBo[q], gB[q] + k0);
        }
        asm volatile("cp.async.commit_group;" ::: "memory");
        s = (s == NSTAGE - 1) ? 0 : s + 1;
    }

    // epilogue (register-resident; pairs (2q,2q+1) live in c0/c1 and c2/c3)
    const int q2 = 2 * (lane & 3);
    if (SWIGLU) {
        const float* bb = bias + (size_t)e * NBROWS + n0 + wn * 48;
        float* actb = g_act + row0 * 2880 + (size_t)(n0 >> 1) + wn * 24;
        float2 bj[NT];
#pragma unroll
        for (int j = 0; j < NT; j++) bj[j] = *(const float2*)(bb + j * 8 + q2);
#pragma unroll
        for (int i = 0; i < 4; i++) {
            const int r1 = wm * 64 + i * 16 + (lane >> 2);
#pragma unroll
            for (int j = 0; j < NT; j++) {
                const int hc = j * 4 + (lane & 3);
#pragma unroll
                for (int hrow = 0; hrow < 2; hrow++) {
                    float g = acc[i][j][2 * hrow] + bj[j].x;
                    float l = acc[i][j][2 * hrow + 1] + bj[j].y;
                    g = fminf(g, 7.0f);
                    l = fminf(fmaxf(l, -7.0f), 7.0f);
                    float sg = 1.0f / (1.0f + __expf(-1.702f * g));
                    actb[(size_t)(r1 + 8 * hrow) * 2880 + hc] =
                        rtf32(g * sg * (l + 1.0f));
                }
            }
        }
    } else {
        const float* bb = bias + (size_t)e * NBROWS + n0 + wn * 48;
        float* ob = Dout + row0 * 2880 + n0 + wn * 48;
        float2 bj[NT];
#pragma unroll
        for (int j = 0; j < NT; j++) bj[j] = *(const float2*)(bb + j * 8 + q2);
#pragma unroll
        for (int i = 0; i < 4; i++) {
            const int r1 = wm * 64 + i * 16 + (lane >> 2);
#pragma unroll
            for (int j = 0; j < NT; j++) {
                const int oc = j * 8 + q2;
#pragma unroll
                for (int hrow = 0; hrow < 2; hrow++) {
                    float2 v;
                    v.x = acc[i][j][2 * hrow] + bj[j].x;
                    v.y = acc[i][j][2 * hrow + 1] + bj[j].y;
                    *(float2*)(ob + (size_t)(r1 + 8 * hrow) * 2880 + oc) = v;
                }
            }
        }
    }
}

// ---------------------------------------------------------------------------
// Launch
// ---------------------------------------------------------------------------
extern "C" void kernel_launch(void* const* d_in, const int* in_sizes, int n_in,
                              void* d_out, int out_size) {
    const float* x = (const float*)d_in[0];
    const float* w1 = (const float*)d_in[2];
    const float* b1 = (const float*)d_in[3];
    const float* w2 = (const float*)d_in[4];
    const float* b2 = (const float*)d_in[5];
    float* out = (float*)d_out;

    cudaFuncSetAttribute(moe_mma_kernel<true>,
                         cudaFuncAttributeMaxDynamicSharedMemorySize, SMEM_BYTES);
    cudaFuncSetAttribute(moe_mma_kernel<false>,
                         cudaFuncAttributeMaxDynamicSharedMemorySize, SMEM_BYTES);

    float* gx;  cudaGetSymbolAddress((void**)&gx, g_x);
    float* gw1; cudaGetSymbolAddress((void**)&gw1, g_w1);
    float* gw2; cudaGetSymbolAddress((void**)&gw2, g_w2);

    const size_t nx = (size_t)16384 * 2880 / 4;
    const size_t nw1 = (size_t)8 * 5760 * 2880 / 4;
    const size_t nw2 = (size_t)8 * 2880 * 2880 / 4;
    round_tf32_kernel<<<4736, 256>>>((const float4*)x, (float4*)gx, nx);
    round_tf32_kernel<<<4736, 256>>>((const float4*)w1, (float4*)gw1, nw1);
    round_tf32_kernel<<<4736, 256>>>((const float4*)w2, (float4*)gw2, nw2);

    // GEMM1: N1=5760 -> 30 n-tiles of 192; GEMM2: D=2880 -> 15 n-tiles
    moe_mma_kernel<true><<<dim3(30, 128), 256, SMEM_BYTES>>>(b1, nullptr);
    moe_mma_kernel<false><<<dim3(15, 128), 256, SMEM_BYTES>>>(b2, out);
}

// round 6
// speedup vs baseline: 1.0668x; 1.0668x over previous
#include <cuda_runtime.h>
#include <cstdint>

// ---------------------------------------------------------------------------
// T=16384, D=H=2880, E=8, C=2048, N1=5760. K=2880 both GEMMs.
// mma.sync tf32, CTA tile 128x288, 12 warps (2M x 6N), warp tile 64x48,
// 3-stage cp.async, one barrier per K-iter. A-side pre-rounded to tf32
// (x via tiny prepass, act rounded at GEMM1 epilogue); B-side (weights)
// read raw with in-loop cvt.rn.tf32.
// ---------------------------------------------------------------------------
#define KDIM 2880
#define BM 128
#define BN 288
#define NT 6
#define BK 32
#define NSTAGE 3
#define NKITER 90
#define LDSF 36
#define A_FLOATS (BM * LDSF)
#define B_FLOATS (BN * LDSF)
#define STAGE_FLOATS (A_FLOATS + B_FLOATS)
#define STAGE_BYTES (STAGE_FLOATS * 4)
#define SMEM_BYTES (NSTAGE * STAGE_BYTES)  // 179712
#define NTHR 384
#define NCHUNK ((BM + BN) * 8)  // 3328 16B-chunks per stage

__device__ float g_x[(size_t)16384 * 2880];
__device__ float g_act[(size_t)16384 * 2880];

__device__ __forceinline__ uint32_t s2u(const void* p) {
    uint32_t a;
    asm("{.reg .u64 t; cvta.to.shared.u64 t, %1; cvt.u32.u64 %0, t;}"
        : "=r"(a) : "l"(p));
    return a;
}
__device__ __forceinline__ float rtf32(float v) {
    uint32_t u;
    asm("cvt.rn.tf32.f32 %0, %1;" : "=r"(u) : "f"(v));
    return __uint_as_float(u);
}
__device__ __forceinline__ uint32_t f2tf32(float v) {
    uint32_t u;
    asm("cvt.rn.tf32.f32 %0, %1;" : "=r"(u) : "f"(v));
    return u;
}
__device__ __forceinline__ void cp16(uint32_t dst, const void* src) {
    asm volatile("cp.async.cg.shared.global [%0], [%1], 16;" ::"r"(dst),
                 "l"(src) : "memory");
}
__device__ __forceinline__ void mma_tf32(float* c, const uint32_t* a,
                                         const uint32_t* b) {
    asm volatile(
        "mma.sync.aligned.m16n8k8.row.col.f32.tf32.tf32.f32 "
        "{%0,%1,%2,%3}, {%4,%5,%6,%7}, {%8,%9}, {%0,%1,%2,%3};"
        : "+f"(c[0]), "+f"(c[1]), "+f"(c[2]), "+f"(c[3])
        : "r"(a[0]), "r"(a[1]), "r"(a[2]), "r"(a[3]), "r"(b[0]), "r"(b[1]));
}

__global__ void round_tf32_kernel(const float4* __restrict__ src,
                                  float4* __restrict__ dst, size_t n4) {
    size_t i = (size_t)blockIdx.x * blockDim.x + threadIdx.x;
    size_t stride = (size_t)gridDim.x * blockDim.x;
    for (; i < n4; i += stride) {
        float4 v = src[i];
        v.x = rtf32(v.x); v.y = rtf32(v.y);
        v.z = rtf32(v.z); v.w = rtf32(v.w);
        dst[i] = v;
    }
}

// ---------------------------------------------------------------------------
template <bool SWIGLU>
__global__ __launch_bounds__(NTHR, 1)
void moe_mma_kernel(const float* __restrict__ Bw, const float* __restrict__ bias,
                    float* __restrict__ Dout) {
    extern __shared__ float smem[];
    const uint32_t smem_u = s2u(smem);

    const int tid = threadIdx.x;
    const int lane = tid & 31;
    const int warp = tid >> 5;
    const int wm = warp & 1;   // 2 warps along M
    const int wn = warp >> 1;  // 6 warps along N

    const int bn = blockIdx.x, bm = blockIdx.y;
    const int e = bm >> 4;
    const size_t row0 = (size_t)bm * BM;
    const int n0 = bn * BN;
    const int NBROWS = SWIGLU ? 5760 : 2880;

    const float* Abase = (SWIGLU ? g_x : g_act) + row0 * KDIM;
    const float* Bbase =
        Bw + (size_t)e * NBROWS * KDIM + (size_t)n0 * KDIM;

    // per-thread cp.async chunks: q=0..7 always valid, q=8 iff tid<256
    const bool has9 = (tid < NCHUNK - 8 * NTHR);  // tid < 256
    const float* gp[9];
    uint32_t so[9];
#pragma unroll
    for (int q = 0; q < 9; q++) {
        int ch = tid + q * NTHR;
        if (q == 8 && !has9) ch = tid;  // dummy (never used)
        if (ch < BM * 8) {
            int r = ch >> 3, c = ch & 7;
            gp[q] = Abase + (size_t)r * KDIM + c * 4;
            so[q] = (r * LDSF + c * 4) * 4;
        } else {
            int c2 = ch - BM * 8;
            int r = c2 >> 3, c = c2 & 7;
            gp[q] = Bbase + (size_t)r * KDIM + c * 4;
            so[q] = (A_FLOATS + r * LDSF + c * 4) * 4;
        }
    }

    // prologue: fill NSTAGE-1 stages
#pragma unroll
    for (int p = 0; p < NSTAGE - 1; p++) {
        uint32_t sb = smem_u + p * STAGE_BYTES;
#pragma unroll
        for (int q = 0; q < 8; q++) cp16(sb + so[q], gp[q] + p * BK);
        if (has9) cp16(sb + so[8], gp[8] + p * BK);
        asm volatile("cp.async.commit_group;" ::: "memory");
    }

    float acc[4][NT][4];
#pragma unroll
    for (int i = 0; i < 4; i++)
#pragma unroll
        for (int j = 0; j < NT; j++)
#pragma unroll
            for (int k = 0; k < 4; k++) acc[i][j][k] = 0.0f;

    const int arow = wm * 64 + (lane >> 2);
    const int kcol = lane & 3;
    const int brow = wn * 48 + (lane >> 2);

    for (int it = 0; it < NKITER; it++) {
        asm volatile("cp.async.wait_group 1;" ::: "memory");
        __syncthreads();

        // refill stage (it+NSTAGE-1)%NSTAGE for k-iter it+NSTAGE-1
        const int kf = it + NSTAGE - 1;
        if (kf < NKITER) {
            uint32_t sb = smem_u + (kf % NSTAGE) * STAGE_BYTES;
            const int k0 = kf * BK;
#pragma unroll
            for (int q = 0; q < 8; q++) cp16(sb + so[q], gp[q] + k0);
            if (has9) cp16(sb + so[8], gp[8] + k0);
        }
        asm volatile("cp.async.commit_group;" ::: "memory");

        const float* sAf = smem + (it % NSTAGE) * STAGE_FLOATS;
        const uint32_t* sA = (const uint32_t*)sAf;
        const float* sB = sAf + A_FLOATS;

#pragma unroll
        for (int kk8 = 0; kk8 < 4; kk8++) {
            const int kk = kk8 * 8;
            uint32_t af[4][4], bf[NT][2];
#pragma unroll
            for (int i = 0; i < 4; i++) {
                const uint32_t* ap = sA + (arow + i * 16) * LDSF + kk + kcol;
                af[i][0] = ap[0];
                af[i][1] = ap[8 * LDSF];
                af[i][2] = ap[4];
                af[i][3] = ap[8 * LDSF + 4];
            }
#pragma unroll
            for (int j = 0; j < NT; j++) {
                const float* bp = sB + (brow + j * 8) * LDSF + kk + kcol;
                bf[j][0] = f2tf32(bp[0]);
                bf[j][1] = f2tf32(bp[4]);
            }
#pragma unroll
            for (int i = 0; i < 4; i++)
#pragma unroll
                for (int j = 0; j < NT; j++) mma_tf32(acc[i][j], af[i], bf[j]);
        }
    }

    // epilogue (register-resident; pairs (2q,2q+1) in c0/c1 and c2/c3)
    const int q2 = 2 * (lane & 3);
    if (SWIGLU) {
        const float* bb = bias + (size_t)e * NBROWS + n0 + wn * 48;
        float* actb = g_act + row0 * 2880 + (size_t)(n0 >> 1) + wn * 24;
        float2 bj[NT];
#pragma unroll
        for (int j = 0; j < NT; j++) bj[j] = *(const float2*)(bb + j * 8 + q2);
#pragma unroll
        for (int i = 0; i < 4; i++) {
            const int r1 = wm * 64 + i * 16 + (lane >> 2);
#pragma unroll
            for (int j = 0; j < NT; j++) {
                const int hc = j * 4 + (lane & 3);
#pragma unroll
                for (int hrow = 0; hrow < 2; hrow++) {
                    float g = acc[i][j][2 * hrow] + bj[j].x;
                    float l = acc[i][j][2 * hrow + 1] + bj[j].y;
                    g = fminf(g, 7.0f);
                    l = fminf(fmaxf(l, -7.0f), 7.0f);
                    float sg = 1.0f / (1.0f + __expf(-1.702f * g));
                    actb[(size_t)(r1 + 8 * hrow) * 2880 + hc] =
                        rtf32(g * sg * (l + 1.0f));
                }
            }
        }
    } else {
        const float* bb = bias + (size_t)e * NBROWS + n0 + wn * 48;
        float* ob = Dout + row0 * 2880 + n0 + wn * 48;
        float2 bj[NT];
#pragma unroll
        for (int j = 0; j < NT; j++) bj[j] = *(const float2*)(bb + j * 8 + q2);
#pragma unroll
        for (int i = 0; i < 4; i++) {
            const int r1 = wm * 64 + i * 16 + (lane >> 2);
#pragma unroll
            for (int j = 0; j < NT; j++) {
                const int oc = j * 8 + q2;
#pragma unroll
                for (int hrow = 0; hrow < 2; hrow++) {
                    float2 v;
                    v.x = acc[i][j][2 * hrow] + bj[j].x;
                    v.y = acc[i][j][2 * hrow + 1] + bj[j].y;
                    *(float2*)(ob + (size_t)(r1 + 8 * hrow) * 2880 + oc) = v;
                }
            }
        }
    }
}

// ---------------------------------------------------------------------------
extern "C" void kernel_launch(void* const* d_in, const int* in_sizes, int n_in,
                              void* d_out, int out_size) {
    const float* x = (const float*)d_in[0];
    const float* w1 = (const float*)d_in[2];
    const float* b1 = (const float*)d_in[3];
    const float* w2 = (const float*)d_in[4];
    const float* b2 = (const float*)d_in[5];
    float* out = (float*)d_out;

    cudaFuncSetAttribute(moe_mma_kernel<true>,
                         cudaFuncAttributeMaxDynamicSharedMemorySize, SMEM_BYTES);
    cudaFuncSetAttribute(moe_mma_kernel<false>,
                         cudaFuncAttributeMaxDynamicSharedMemorySize, SMEM_BYTES);

    float* gx;
    cudaGetSymbolAddress((void**)&gx, g_x);
    const size_t nx = (size_t)16384 * 2880 / 4;
    round_tf32_kernel<<<2048, 256>>>((const float4*)x, (float4*)gx, nx);

    // GEMM1: 5760/288 = 20 n-tiles; GEMM2: 2880/288 = 10 n-tiles
    moe_mma_kernel<true><<<dim3(20, 128), NTHR, SMEM_BYTES>>>(w1, b1, nullptr);
    moe_mma_kernel<false><<<dim3(10, 128), NTHR, SMEM_BYTES>>>(w2, b2, out);
}

// round 7
// speedup vs baseline: 1.0680x; 1.0011x over previous
#include <cuda_runtime.h>
#include <cstdint>

// ---------------------------------------------------------------------------
// T=16384, D=H=2880, E=8, C=2048, N1=5760. K=2880 both GEMMs.
// mma.sync tf32. CTA tile 128x320, 8 warps (2M x 4N), warp tile 64x80
// (crossbar-balanced: 4/b + 2/a = 0.9 < 1). 3-stage cp.async, 1 barrier/iter.
// A-side pre-rounded tf32 (x prepass; act rounded at GEMM1 epilogue);
// B-side (weights) raw with in-loop cvt.rn.tf32.
// ---------------------------------------------------------------------------
#define KDIM 2880
#define BM 128
#define BN 320
#define NT 10              // n8-subtiles per warp -> warp tile 64 x 80
#define BK 32
#define NSTAGE 3
#define NKITER 90
#define LDSF 36
#define A_FLOATS (BM * LDSF)
#define B_FLOATS (BN * LDSF)
#define STAGE_FLOATS (A_FLOATS + B_FLOATS)
#define STAGE_BYTES (STAGE_FLOATS * 4)
#define SMEM_BYTES (NSTAGE * STAGE_BYTES)  // 193536
#define NTHR 256

__device__ float g_x[(size_t)16384 * 2880];
__device__ float g_act[(size_t)16384 * 2880];

__device__ __forceinline__ uint32_t s2u(const void* p) {
    uint32_t a;
    asm("{.reg .u64 t; cvta.to.shared.u64 t, %1; cvt.u32.u64 %0, t;}"
        : "=r"(a) : "l"(p));
    return a;
}
__device__ __forceinline__ float rtf32(float v) {
    uint32_t u;
    asm("cvt.rn.tf32.f32 %0, %1;" : "=r"(u) : "f"(v));
    return __uint_as_float(u);
}
__device__ __forceinline__ uint32_t f2tf32(float v) {
    uint32_t u;
    asm("cvt.rn.tf32.f32 %0, %1;" : "=r"(u) : "f"(v));
    return u;
}
__device__ __forceinline__ void cp16(uint32_t dst, const void* src) {
    asm volatile("cp.async.cg.shared.global [%0], [%1], 16;" ::"r"(dst),
                 "l"(src) : "memory");
}
__device__ __forceinline__ void mma_tf32(float* c, const uint32_t* a,
                                         const uint32_t* b) {
    asm volatile(
        "mma.sync.aligned.m16n8k8.row.col.f32.tf32.tf32.f32 "
        "{%0,%1,%2,%3}, {%4,%5,%6,%7}, {%8,%9}, {%0,%1,%2,%3};"
        : "+f"(c[0]), "+f"(c[1]), "+f"(c[2]), "+f"(c[3])
        : "r"(a[0]), "r"(a[1]), "r"(a[2]), "r"(a[3]), "r"(b[0]), "r"(b[1]));
}

__global__ void round_tf32_kernel(const float4* __restrict__ src,
                                  float4* __restrict__ dst, size_t n4) {
    size_t i = (size_t)blockIdx.x * blockDim.x + threadIdx.x;
    size_t stride = (size_t)gridDim.x * blockDim.x;
    for (; i < n4; i += stride) {
        float4 v = src[i];
        v.x = rtf32(v.x); v.y = rtf32(v.y);
        v.z = rtf32(v.z); v.w = rtf32(v.w);
        dst[i] = v;
    }
}

// ---------------------------------------------------------------------------
template <bool SWIGLU>
__global__ __launch_bounds__(NTHR, 1)
void moe_mma_kernel(const float* __restrict__ Bw, const float* __restrict__ bias,
                    float* __restrict__ Dout) {
    extern __shared__ float smem[];
    const uint32_t smem_u = s2u(smem);

    const int tid = threadIdx.x;
    const int lane = tid & 31;
    const int warp = tid >> 5;
    const int wm = warp & 1;   // 2 warps along M (64 rows)
    const int wn = warp >> 1;  // 4 warps along N (80 cols)

    const int bn = blockIdx.x, bm = blockIdx.y;
    const int e = bm >> 4;  // 16 m-tiles per expert (2048/128)
    const size_t row0 = (size_t)bm * BM;
    const int n0 = bn * BN;
    const int NBROWS = SWIGLU ? 5760 : 2880;

    const float* Abase = (SWIGLU ? g_x : g_act) + row0 * KDIM;
    const float* Bbase = Bw + (size_t)e * NBROWS * KDIM + (size_t)n0 * KDIM;

    // copy map: 448 rows x 8 chunks = 3584 = 14 x 256 exactly.
    // q=0..3 -> A rows (128), q=4..13 -> B rows (320). No branches.
    const int crb = tid >> 3;          // 0..31
    const int cc4 = (tid & 7) * 4;     // k-offset in floats
    const float* Acp = Abase + (size_t)crb * KDIM + cc4;
    const float* Bcp = Bbase + (size_t)crb * KDIM + cc4;
    const uint32_t sAo = smem_u + (crb * LDSF + cc4) * 4;
    const uint32_t sBo = smem_u + (A_FLOATS + crb * LDSF + cc4) * 4;
    const size_t gstep = (size_t)32 * KDIM;

    // prologue: fill NSTAGE-1 stages
#pragma unroll
    for (int p = 0; p < NSTAGE - 1; p++) {
        const uint32_t sb = p * STAGE_BYTES;
        const int k0 = p * BK;
#pragma unroll
        for (int q = 0; q < 4; q++)
            cp16(sAo + sb + q * (32 * LDSF * 4), Acp + q * gstep + k0);
#pragma unroll
        for (int q = 0; q < 10; q++)
            cp16(sBo + sb + q * (32 * LDSF * 4), Bcp + q * gstep + k0);
        asm volatile("cp.async.commit_group;" ::: "memory");
    }

    float acc[4][NT][4];
#pragma unroll
    for (int i = 0; i < 4; i++)
#pragma unroll
        for (int j = 0; j < NT; j++)
#pragma unroll
            for (int k = 0; k < 4; k++) acc[i][j][k] = 0.0f;

    const int arow = wm * 64 + (lane >> 2);
    const int kcol = lane & 3;
    const int brow = wn * 80 + (lane >> 2);

    for (int it = 0; it < NKITER; it++) {
        asm volatile("cp.async.wait_group 1;" ::: "memory");
        __syncthreads();

        // refill stage for k-iter it+NSTAGE-1
        const int kf = it + NSTAGE - 1;
        if (kf < NKITER) {
            const uint32_t sb = (kf % NSTAGE) * STAGE_BYTES;
            const int k0 = kf * BK;
#pragma unroll
            for (int q = 0; q < 4; q++)
                cp16(sAo + sb + q * (32 * LDSF * 4), Acp + q * gstep + k0);
#pragma unroll
            for (int q = 0; q < 10; q++)
                cp16(sBo + sb + q * (32 * LDSF * 4), Bcp + q * gstep + k0);
        }
        asm volatile("cp.async.commit_group;" ::: "memory");

        const float* sAf = smem + (it % NSTAGE) * STAGE_FLOATS;
        const uint32_t* sA = (const uint32_t*)sAf;
        const float* sB = sAf + A_FLOATS;

#pragma unroll
        for (int kk8 = 0; kk8 < 4; kk8++) {
            const int kk = kk8 * 8;
            uint32_t af[4][4], bf[NT][2];
#pragma unroll
            for (int i = 0; i < 4; i++) {
                const uint32_t* ap = sA + (arow + i * 16) * LDSF + kk + kcol;
                af[i][0] = ap[0];
                af[i][1] = ap[8 * LDSF];
                af[i][2] = ap[4];
                af[i][3] = ap[8 * LDSF + 4];
            }
#pragma unroll
            for (int j = 0; j < NT; j++) {
                const float* bp = sB + (brow + j * 8) * LDSF + kk + kcol;
                bf[j][0] = f2tf32(bp[0]);
                bf[j][1] = f2tf32(bp[4]);
            }
#pragma unroll
            for (int i = 0; i < 4; i++)
#pragma unroll
                for (int j = 0; j < NT; j++) mma_tf32(acc[i][j], af[i], bf[j]);
        }
    }

    // epilogue (register-resident; pairs (2q,2q+1) in c0/c1 and c2/c3)
    const int q2 = 2 * (lane & 3);
    if (SWIGLU) {
        const float* bb = bias + (size_t)e * NBROWS + n0 + wn * 80;
        float* actb = g_act + row0 * 2880 + (size_t)(n0 >> 1) + wn * 40;
        float2 bj[NT];
#pragma unroll
        for (int j = 0; j < NT; j++) bj[j] = *(const float2*)(bb + j * 8 + q2);
#pragma unroll
        for (int i = 0; i < 4; i++) {
            const int r1 = wm * 64 + i * 16 + (lane >> 2);
#pragma unroll
            for (int j = 0; j < NT; j++) {
                const int hc = j * 4 + (lane & 3);
#pragma unroll
                for (int hrow = 0; hrow < 2; hrow++) {
                    float g = acc[i][j][2 * hrow] + bj[j].x;
                    float l = acc[i][j][2 * hrow + 1] + bj[j].y;
                    g = fminf(g, 7.0f);
                    l = fminf(fmaxf(l, -7.0f), 7.0f);
                    float sg = 1.0f / (1.0f + __expf(-1.702f * g));
                    actb[(size_t)(r1 + 8 * hrow) * 2880 + hc] =
                        rtf32(g * sg * (l + 1.0f));
                }
            }
        }
    } else {
        const float* bb = bias + (size_t)e * NBROWS + n0 + wn * 80;
        float* ob = Dout + row0 * 2880 + n0 + wn * 80;
        float2 bj[NT];
#pragma unroll
        for (int j = 0; j < NT; j++) bj[j] = *(const float2*)(bb + j * 8 + q2);
#pragma unroll
        for (int i = 0; i < 4; i++) {
            const int r1 = wm * 64 + i * 16 + (lane >> 2);
#pragma unroll
            for (int j = 0; j < NT; j++) {
                const int oc = j * 8 + q2;
#pragma unroll
                for (int hrow = 0; hrow < 2; hrow++) {
                    float2 v;
                    v.x = acc[i][j][2 * hrow] + bj[j].x;
                    v.y = acc[i][j][2 * hrow + 1] + bj[j].y;
                    *(float2*)(ob + (size_t)(r1 + 8 * hrow) * 2880 + oc) = v;
                }
            }
        }
    }
}

// ---------------------------------------------------------------------------
extern "C" void kernel_launch(void* const* d_in, const int* in_sizes, int n_in,
                              void* d_out, int out_size) {
    const float* x = (const float*)d_in[0];
    const float* w1 = (const float*)d_in[2];
    const float* b1 = (const float*)d_in[3];
    const float* w2 = (const float*)d_in[4];
    const float* b2 = (const float*)d_in[5];
    float* out = (float*)d_out;

    cudaFuncSetAttribute(moe_mma_kernel<true>,
                         cudaFuncAttributeMaxDynamicSharedMemorySize, SMEM_BYTES);
    cudaFuncSetAttribute(moe_mma_kernel<false>,
                         cudaFuncAttributeMaxDynamicSharedMemorySize, SMEM_BYTES);

    float* gx;
    cudaGetSymbolAddress((void**)&gx, g_x);
    const size_t nx = (size_t)16384 * 2880 / 4;
    round_tf32_kernel<<<2048, 256>>>((const float4*)x, (float4*)gx, nx);

    // GEMM1: 5760/320 = 18 n-tiles; GEMM2: 2880/320 = 9 n-tiles
    moe_mma_kernel<true><<<dim3(18, 128), NTHR, SMEM_BYTES>>>(w1, b1, nullptr);
    moe_mma_kernel<false><<<dim3(9, 128), NTHR, SMEM_BYTES>>>(w2, b2, out);
}